// round 1
// baseline (speedup 1.0000x reference)
#include <cuda_runtime.h>
#include <math.h>

// Inputs (metadata order): a [4096,128] f32, p [4096,128] f32, n [4096,128] f32.
// Output: 1 float scalar.

#define B_SIZE 4096
#define DIM    128
#define NTOT   12288          // 3*B
#define TILE   128
#define NTILES 96             // NTOT / TILE
#define LDP    132            // padded leading dim for smem tiles
#define MARGIN 0.4f
#define ALPHA  0.01f

#define SMEM_BYTES (2 * TILE * LDP * 4)   // 135168 bytes

// Scratch (static device arrays — no allocation)
__device__ float        g_sq[NTOT];       // ||emb_i||^2
__device__ unsigned int g_rowmin[NTOT];   // min neg d^2, as uint bits (nonneg float order == uint order)
__device__ float        g_posmax[NTOT];   // max positive d^2
__device__ float        g_regpart[NTOT];  // per-row sum of (|x|-1)^2

__device__ __forceinline__ const float* row_ptr(const float* a, const float* p,
                                                const float* n, int i) {
    if (i < B_SIZE)       return a + (size_t)i * DIM;
    if (i < 2 * B_SIZE)   return p + (size_t)(i - B_SIZE) * DIM;
    return n + (size_t)(i - 2 * B_SIZE) * DIM;
}

// ---------------------------------------------------------------------------
// prep: per-row ||x||^2, reg partial, pos_max d^2, init rowmin
// grid = NTOT blocks, 128 threads (one thread per dim element)
// ---------------------------------------------------------------------------
__global__ void prep_kernel(const float* __restrict__ a,
                            const float* __restrict__ p,
                            const float* __restrict__ n) {
    int i = blockIdx.x;
    int t = threadIdx.x;

    const float* r = row_ptr(a, p, n, i);
    float x = r[t];

    int c = i & (B_SIZE - 1);
    int p1, p2;
    if (i < B_SIZE)            { p1 = c + B_SIZE; p2 = c + 2 * B_SIZE; }
    else if (i < 2 * B_SIZE)   { p1 = c;          p2 = c + 2 * B_SIZE; }
    else                       { p1 = c;          p2 = c + B_SIZE;     }

    float y1 = row_ptr(a, p, n, p1)[t];
    float y2 = row_ptr(a, p, n, p2)[t];

    float sq  = x * x;
    float ax  = fabsf(x) - 1.0f;
    float reg = ax * ax;
    float e1  = (x - y1) * (x - y1);
    float e2  = (x - y2) * (x - y2);

    #pragma unroll
    for (int ofs = 16; ofs; ofs >>= 1) {
        sq  += __shfl_xor_sync(0xffffffffu, sq,  ofs);
        reg += __shfl_xor_sync(0xffffffffu, reg, ofs);
        e1  += __shfl_xor_sync(0xffffffffu, e1,  ofs);
        e2  += __shfl_xor_sync(0xffffffffu, e2,  ofs);
    }

    __shared__ float s[4][4];
    int w = t >> 5, l = t & 31;
    if (l == 0) { s[w][0] = sq; s[w][1] = reg; s[w][2] = e1; s[w][3] = e2; }
    __syncthreads();
    if (t == 0) {
        float tsq  = s[0][0] + s[1][0] + s[2][0] + s[3][0];
        float treg = s[0][1] + s[1][1] + s[2][1] + s[3][1];
        float te1  = s[0][2] + s[1][2] + s[2][2] + s[3][2];
        float te2  = s[0][3] + s[1][3] + s[2][3] + s[3][3];
        g_sq[i]      = tsq;
        g_regpart[i] = treg;
        g_posmax[i]  = fmaxf(te1, te2);
        g_rowmin[i]  = 0x7f800000u;  // +inf bits
    }
}

// ---------------------------------------------------------------------------
// tile: 128x128 d^2 tile per block, upper-triangle tiles only.
// Tracks per-row and per-col min(d^2) with masking, atomicMin to g_rowmin.
// ---------------------------------------------------------------------------
__global__ void __launch_bounds__(256, 1)
tile_kernel(const float* __restrict__ a,
            const float* __restrict__ p,
            const float* __restrict__ n) {
    int bj = blockIdx.x;   // column tile
    int bi = blockIdx.y;   // row tile
    if (bj < bi) return;   // symmetry: only upper triangle

    extern __shared__ float smem[];
    float* As = smem;                 // [k][m] : As[k*LDP + m]
    float* Bs = smem + TILE * LDP;

    int tid = threadIdx.x;
    int rowbase = bi * TILE;
    int colbase = bj * TILE;
    const float* Ap = row_ptr(a, p, n, rowbase);  // tile lies fully in one segment
    const float* Bp = row_ptr(a, p, n, colbase);

    // Coalesced global read, transposed smem store (4-way bank conflict on store,
    // once per block — acceptable vs. 128-iter compute loop).
    #pragma unroll
    for (int e = tid; e < TILE * DIM; e += 256) {
        int m = e >> 7, k = e & 127;
        As[k * LDP + m] = Ap[m * DIM + k];
        Bs[k * LDP + m] = Bp[m * DIM + k];
    }
    __syncthreads();

    int tx = tid & 15;     // column group
    int ty = tid >> 4;     // row group

    float acc[8][8];
    #pragma unroll
    for (int u = 0; u < 8; u++)
        #pragma unroll
        for (int v = 0; v < 8; v++) acc[u][v] = 0.0f;

    for (int k = 0; k < DIM; ++k) {
        const float4 a0 = *reinterpret_cast<const float4*>(&As[k * LDP + ty * 8]);
        const float4 a1 = *reinterpret_cast<const float4*>(&As[k * LDP + ty * 8 + 4]);
        const float4 b0 = *reinterpret_cast<const float4*>(&Bs[k * LDP + tx * 8]);
        const float4 b1 = *reinterpret_cast<const float4*>(&Bs[k * LDP + tx * 8 + 4]);
        float av[8] = {a0.x, a0.y, a0.z, a0.w, a1.x, a1.y, a1.z, a1.w};
        float bv[8] = {b0.x, b0.y, b0.z, b0.w, b1.x, b1.y, b1.z, b1.w};
        #pragma unroll
        for (int u = 0; u < 8; u++)
            #pragma unroll
            for (int v = 0; v < 8; v++)
                acc[u][v] = fmaf(av[u], bv[v], acc[u][v]);
    }

    // Epilogue: d^2 = sq_i + sq_j - 2*dot, masked, min per row / col
    float sqi[8], sqj[8];
    #pragma unroll
    for (int u = 0; u < 8; u++) sqi[u] = g_sq[rowbase + ty * 8 + u];
    #pragma unroll
    for (int v = 0; v < 8; v++) sqj[v] = g_sq[colbase + tx * 8 + v];

    // same label iff (i-j) % 4096 == 0 -> (bi%32==bj%32) && local diag
    bool diag = ((bi & 31) == (bj & 31));
    const float FINF = __int_as_float(0x7f800000);

    float rmin[8], cmin[8];
    #pragma unroll
    for (int u = 0; u < 8; u++) rmin[u] = FINF;
    #pragma unroll
    for (int v = 0; v < 8; v++) cmin[v] = FINF;

    #pragma unroll
    for (int u = 0; u < 8; u++) {
        #pragma unroll
        for (int v = 0; v < 8; v++) {
            float d2 = fmaxf(sqi[u] + sqj[v] - 2.0f * acc[u][v], 0.0f);
            if (diag && (ty * 8 + u) == (tx * 8 + v)) d2 = FINF;
            rmin[u] = fminf(rmin[u], d2);
            cmin[v] = fminf(cmin[v], d2);
        }
    }

    // Row min: reduce across tx (lane bits 0..3) via shuffle
    #pragma unroll
    for (int u = 0; u < 8; u++) {
        #pragma unroll
        for (int ofs = 8; ofs; ofs >>= 1)
            rmin[u] = fminf(rmin[u], __shfl_xor_sync(0xffffffffu, rmin[u], ofs));
    }
    if (tx == 0) {
        #pragma unroll
        for (int u = 0; u < 8; u++)
            atomicMin(&g_rowmin[rowbase + ty * 8 + u], __float_as_uint(rmin[u]));
    }

    // Col min: reduce across ty via smem atomics (reuse tile smem)
    __syncthreads();
    unsigned int* sCol = reinterpret_cast<unsigned int*>(smem);
    if (tid < TILE) sCol[tid] = 0x7f800000u;
    __syncthreads();
    #pragma unroll
    for (int v = 0; v < 8; v++)
        atomicMin(&sCol[tx * 8 + v], __float_as_uint(cmin[v]));
    __syncthreads();
    if (tid < TILE) atomicMin(&g_rowmin[colbase + tid], sCol[tid]);
}

// ---------------------------------------------------------------------------
// finalize: per-row hinge + means -> scalar
// ---------------------------------------------------------------------------
__global__ void finalize_kernel(float* __restrict__ out) {
    __shared__ float sl[1024];
    __shared__ float sr[1024];
    int t = threadIdx.x;
    float ls = 0.0f, rs = 0.0f;
    for (int i = t; i < NTOT; i += 1024) {
        float pm = g_posmax[i];
        float nm = __uint_as_float(g_rowmin[i]);
        float pd = (pm > 0.0f) ? sqrtf(pm) : 0.0f;
        float nd = (nm > 0.0f) ? sqrtf(nm) : 0.0f;
        ls += fmaxf(pd - nd + MARGIN, 0.0f);
        rs += g_regpart[i];
    }
    sl[t] = ls; sr[t] = rs;
    __syncthreads();
    #pragma unroll
    for (int s = 512; s; s >>= 1) {
        if (t < s) { sl[t] += sl[t + s]; sr[t] += sr[t + s]; }
        __syncthreads();
    }
    if (t == 0)
        out[0] = sl[0] / (float)NTOT + ALPHA * (sr[0] / (float)(NTOT * DIM));
}

// ---------------------------------------------------------------------------
extern "C" void kernel_launch(void* const* d_in, const int* in_sizes, int n_in,
                              void* d_out, int out_size) {
    const float* a = (const float*)d_in[0];
    const float* p = (const float*)d_in[1];
    const float* n = (const float*)d_in[2];
    float* out = (float*)d_out;

    cudaFuncSetAttribute(tile_kernel,
                         cudaFuncAttributeMaxDynamicSharedMemorySize, SMEM_BYTES);

    prep_kernel<<<NTOT, 128>>>(a, p, n);
    tile_kernel<<<dim3(NTILES, NTILES), 256, SMEM_BYTES>>>(a, p, n);
    finalize_kernel<<<1, 1024>>>(out);
}

// round 3
// speedup vs baseline: 1.6324x; 1.6324x over previous
#include <cuda_runtime.h>
#include <cuda_bf16.h>
#include <cstdint>
#include <math.h>

// Inputs: a [4096,128] f32, p [4096,128] f32, n [4096,128] f32. Output: 1 f32.

#define B_SIZE 4096
#define DIM    128
#define NTOT   12288
#define NTILES 96
#define GSPLIT 3
#define JTILES (NTILES / GSPLIT)   // 32
#define TPB    256
#define MARGIN 0.4f
#define ALPHA  0.01f

// ---- smem layout (bytes) ----
// sqj double buffer, A (hi/lo) resident, B (hi/lo) double buffered.
#define OFF_SQJ(b) ((b) * 512)
#define OFF_AHI    1024
#define OFF_ALO    (OFF_AHI + 32768)
#define OFF_BHI(b) (66560 + (b) * 65536)
#define OFF_BLO(b) (OFF_BHI(b) + 32768)
#define SMEM_TOTAL (66560 + 2 * 65536)   // 197632

// ---- device scratch ----
__device__ float          g_sq[NTOT];
__device__ unsigned int   g_rowmin[NTOT];
__device__ float          g_posmax[NTOT];
__device__ float          g_regpart[NTOT];
__device__ __nv_bfloat16  g_hi[NTOT * DIM];
__device__ __nv_bfloat16  g_lo[NTOT * DIM];

// ---- helpers ----
__device__ __forceinline__ uint32_t smem_u32(const void* p) {
    uint32_t a;
    asm("{ .reg .u64 t; cvta.to.shared.u64 t, %1; cvt.u32.u64 %0, t; }"
        : "=r"(a) : "l"(p));
    return a;
}
__device__ __forceinline__ void cp16(uint32_t dst, const void* src) {
    asm volatile("cp.async.cg.shared.global [%0], [%1], 16;"
                 :: "r"(dst), "l"(src));
}
#define CP_COMMIT() asm volatile("cp.async.commit_group;" ::: "memory")
#define CP_WAIT(n)  asm volatile("cp.async.wait_group %0;" :: "n"(n) : "memory")

__device__ __forceinline__ void ldsm4(uint32_t* r, uint32_t addr) {
    asm volatile("ldmatrix.sync.aligned.m8n8.x4.shared.b16 {%0,%1,%2,%3}, [%4];"
                 : "=r"(r[0]), "=r"(r[1]), "=r"(r[2]), "=r"(r[3]) : "r"(addr));
}
__device__ __forceinline__ void mma16816(float* d, const uint32_t* a,
                                         uint32_t b0, uint32_t b1) {
    asm volatile("mma.sync.aligned.m16n8k16.row.col.f32.bf16.bf16.f32 "
                 "{%0,%1,%2,%3}, {%4,%5,%6,%7}, {%8,%9}, {%0,%1,%2,%3};"
                 : "+f"(d[0]), "+f"(d[1]), "+f"(d[2]), "+f"(d[3])
                 : "r"(a[0]), "r"(a[1]), "r"(a[2]), "r"(a[3]),
                   "r"(b0), "r"(b1));
}

__device__ __forceinline__ const float* row_ptr(const float* a, const float* p,
                                                const float* n, int i) {
    if (i < B_SIZE)     return a + (size_t)i * DIM;
    if (i < 2 * B_SIZE) return p + (size_t)(i - B_SIZE) * DIM;
    return n + (size_t)(i - 2 * B_SIZE) * DIM;
}

// ---------------------------------------------------------------------------
// prep: sq / reg / posmax (fp32 exact) + bf16 hi/lo split. One warp per row.
// ---------------------------------------------------------------------------
__global__ void __launch_bounds__(256) prep_kernel(const float* __restrict__ a,
                                                   const float* __restrict__ p,
                                                   const float* __restrict__ n) {
    int gw   = (blockIdx.x * 256 + threadIdx.x) >> 5;
    int lane = threadIdx.x & 31;

    int c = gw & (B_SIZE - 1);
    int p1, p2;
    if (gw < B_SIZE)          { p1 = c + B_SIZE; p2 = c + 2 * B_SIZE; }
    else if (gw < 2 * B_SIZE) { p1 = c;          p2 = c + 2 * B_SIZE; }
    else                      { p1 = c;          p2 = c + B_SIZE;     }

    float4 x  = reinterpret_cast<const float4*>(row_ptr(a, p, n, gw))[lane];
    float4 y1 = reinterpret_cast<const float4*>(row_ptr(a, p, n, p1))[lane];
    float4 y2 = reinterpret_cast<const float4*>(row_ptr(a, p, n, p2))[lane];

    float xs[4]  = {x.x, x.y, x.z, x.w};
    float y1s[4] = {y1.x, y1.y, y1.z, y1.w};
    float y2s[4] = {y2.x, y2.y, y2.z, y2.w};

    float sq = 0.f, reg = 0.f, e1 = 0.f, e2 = 0.f;
    #pragma unroll
    for (int i = 0; i < 4; i++) {
        sq += xs[i] * xs[i];
        float ax = fabsf(xs[i]) - 1.0f;
        reg += ax * ax;
        float d1 = xs[i] - y1s[i]; e1 += d1 * d1;
        float d2 = xs[i] - y2s[i]; e2 += d2 * d2;
    }
    #pragma unroll
    for (int ofs = 16; ofs; ofs >>= 1) {
        sq  += __shfl_xor_sync(0xffffffffu, sq,  ofs);
        reg += __shfl_xor_sync(0xffffffffu, reg, ofs);
        e1  += __shfl_xor_sync(0xffffffffu, e1,  ofs);
        e2  += __shfl_xor_sync(0xffffffffu, e2,  ofs);
    }
    if (lane == 0) {
        g_sq[gw]      = sq;
        g_regpart[gw] = reg;
        g_posmax[gw]  = fmaxf(e1, e2);
        g_rowmin[gw]  = 0x7f800000u;   // +inf bits
    }

    unsigned hu0 = 0, hu1 = 0, lu0 = 0, lu1 = 0;
    #pragma unroll
    for (int i = 0; i < 4; i++) {
        __nv_bfloat16 h = __float2bfloat16(xs[i]);
        __nv_bfloat16 l = __float2bfloat16(xs[i] - __bfloat162float(h));
        unsigned hb = __bfloat16_as_ushort(h);
        unsigned lb = __bfloat16_as_ushort(l);
        if (i < 2) { hu0 |= hb << (16 * i);       lu0 |= lb << (16 * i); }
        else       { hu1 |= hb << (16 * (i - 2)); lu1 |= lb << (16 * (i - 2)); }
    }
    reinterpret_cast<uint2*>(g_hi)[gw * 32 + lane] = make_uint2(hu0, hu1);
    reinterpret_cast<uint2*>(g_lo)[gw * 32 + lane] = make_uint2(lu0, lu1);
}

// ---------------------------------------------------------------------------
// prefetch one 128x128 bf16 tile (32KB) global -> swizzled smem via cp.async.
// smem layout: row m at off + m*256; 16B chunk c stored at chunk (c ^ (m&7)).
// ---------------------------------------------------------------------------
__device__ __forceinline__ void prefetch_tile(const __nv_bfloat16* __restrict__ g,
                                              int rowbase, uint32_t sm_off,
                                              uint32_t sb, int tid) {
    const uint4* src = reinterpret_cast<const uint4*>(g) + (size_t)rowbase * 16;
    #pragma unroll
    for (int i = 0; i < 8; i++) {
        int ch = tid + i * 256;
        int m = ch >> 4, c = ch & 15;
        uint32_t dst = sb + sm_off + ((uint32_t)m << 8) + ((uint32_t)(c ^ (m & 7)) << 4);
        cp16(dst, src + ch);
    }
}

// ---------------------------------------------------------------------------
// tile kernel: persistent row-block, 32 column tiles, HMMA bf16 3-product.
// ---------------------------------------------------------------------------
__global__ void __launch_bounds__(TPB, 1) tile_kernel() {
    extern __shared__ char smem[];
    uint32_t sb = smem_u32(smem);
    const int tid  = threadIdx.x;
    const int wid  = tid >> 5;
    const int lane = tid & 31;

    const int bi      = blockIdx.x / GSPLIT;
    const int third   = blockIdx.x % GSPLIT;
    const int rowbase = bi * 128;
    const int jt0     = third * JTILES;

    // warp layout: 2 warps in M (64 rows each) x 4 warps in N (32 cols each)
    const int wy  = wid & 1,  wx = wid >> 1;
    const int m0w = wy * 64,  n0w = wx * 32;

    // initial prefetch: A tiles + B tile 0 + sqj0  (one group)
    prefetch_tile(g_hi, rowbase, OFF_AHI, sb, tid);
    prefetch_tile(g_lo, rowbase, OFF_ALO, sb, tid);
    prefetch_tile(g_hi, jt0 * 128, OFF_BHI(0), sb, tid);
    prefetch_tile(g_lo, jt0 * 128, OFF_BLO(0), sb, tid);
    if (tid < 32) cp16(sb + OFF_SQJ(0) + tid * 16, g_sq + jt0 * 128 + tid * 4);
    CP_COMMIT();

    // per-thread row metadata
    float sqi[4][2];
    float rmin[4][2];
    #pragma unroll
    for (int mt = 0; mt < 4; mt++)
        #pragma unroll
        for (int h = 0; h < 2; h++) {
            int r = m0w + mt * 16 + (lane >> 2) + h * 8;
            sqi[mt][h]  = g_sq[rowbase + r];
            rmin[mt][h] = __int_as_float(0x7f800000);
        }

    // ldmatrix lane address components (tile-local)
    const int a_rbit = (lane >> 3) & 1;          // row +8 selector for A
    const int a_cbit = (lane >> 4) & 1;          // k-chunk +1 selector for A
    const int b_rbit = (lane >> 4) & 1;          // row +8 selector for B
    const int b_cbit = (lane >> 3) & 1;          // k-chunk +1 selector for B
    const int l7 = lane & 7;

    for (int t = 0; t < JTILES; t++) {
        const int b  = t & 1, nb = b ^ 1;
        const int jt = jt0 + t;

        if (t + 1 < JTILES) {
            prefetch_tile(g_hi, (jt + 1) * 128, OFF_BHI(nb), sb, tid);
            prefetch_tile(g_lo, (jt + 1) * 128, OFF_BLO(nb), sb, tid);
            if (tid < 32)
                cp16(sb + OFF_SQJ(nb) + tid * 16, g_sq + (jt + 1) * 128 + tid * 4);
            CP_COMMIT();
            CP_WAIT(1);
        } else {
            CP_WAIT(0);
        }
        __syncthreads();

        // ---- MMA: 24 k16 slabs = (Hi*Hi, Hi*Lo, Lo*Hi) x 8 ----
        float acc[4][4][4];
        #pragma unroll
        for (int mt = 0; mt < 4; mt++)
            #pragma unroll
            for (int nt = 0; nt < 4; nt++)
                #pragma unroll
                for (int k = 0; k < 4; k++) acc[mt][nt][k] = 0.0f;

        #pragma unroll
        for (int s = 0; s < 24; s++) {
            const int pr = s >> 3, ks = s & 7;
            const uint32_t Ab = sb + ((pr < 2) ? OFF_AHI : OFF_ALO);
            const uint32_t Bb = sb + ((pr == 1) ? (uint32_t)OFF_BLO(b)
                                                : (uint32_t)OFF_BHI(b));
            const int c0 = ks * 2;

            uint32_t af[4][4];
            #pragma unroll
            for (int mt = 0; mt < 4; mt++) {
                int row = m0w + mt * 16 + l7 + a_rbit * 8;
                int cc  = c0 + a_cbit;
                ldsm4(af[mt], Ab + ((uint32_t)row << 8) +
                              ((uint32_t)(cc ^ (row & 7)) << 4));
            }
            uint32_t bf[2][4];
            #pragma unroll
            for (int bt = 0; bt < 2; bt++) {
                int row = n0w + bt * 16 + l7 + b_rbit * 8;
                int cc  = c0 + b_cbit;
                ldsm4(bf[bt], Bb + ((uint32_t)row << 8) +
                              ((uint32_t)(cc ^ (row & 7)) << 4));
            }
            #pragma unroll
            for (int mt = 0; mt < 4; mt++)
                #pragma unroll
                for (int nt = 0; nt < 4; nt++)
                    mma16816(acc[mt][nt], af[mt],
                             bf[nt >> 1][(nt & 1) * 2],
                             bf[nt >> 1][(nt & 1) * 2 + 1]);
        }

        // ---- epilogue: d^2 = sqi + sqj - 2*dot, mask, running min ----
        const float* sqj = reinterpret_cast<const float*>(smem + OFF_SQJ(b));
        const bool diag = ((bi & 31) == (jt & 31));
        const float FINF = __int_as_float(0x7f800000);

        #pragma unroll
        for (int mt = 0; mt < 4; mt++) {
            const int r0 = m0w + mt * 16 + (lane >> 2);
            const int r1 = r0 + 8;
            #pragma unroll
            for (int nt = 0; nt < 4; nt++) {
                const int c0i = n0w + nt * 8 + (lane & 3) * 2;
                float2 sj = *reinterpret_cast<const float2*>(&sqj[c0i]);
                float d00 = fmaxf(fmaf(acc[mt][nt][0], -2.f, sqi[mt][0] + sj.x), 0.f);
                float d01 = fmaxf(fmaf(acc[mt][nt][1], -2.f, sqi[mt][0] + sj.y), 0.f);
                float d10 = fmaxf(fmaf(acc[mt][nt][2], -2.f, sqi[mt][1] + sj.x), 0.f);
                float d11 = fmaxf(fmaf(acc[mt][nt][3], -2.f, sqi[mt][1] + sj.y), 0.f);
                if (diag) {
                    if (r0 == c0i)     d00 = FINF;
                    if (r0 == c0i + 1) d01 = FINF;
                    if (r1 == c0i)     d10 = FINF;
                    if (r1 == c0i + 1) d11 = FINF;
                }
                rmin[mt][0] = fminf(rmin[mt][0], fminf(d00, d01));
                rmin[mt][1] = fminf(rmin[mt][1], fminf(d10, d11));
            }
        }
        __syncthreads();   // everyone done reading buf b before it is refilled
    }

    // ---- final row-min reduction: lanes sharing a row, then global atomic ----
    #pragma unroll
    for (int mt = 0; mt < 4; mt++)
        #pragma unroll
        for (int h = 0; h < 2; h++) {
            float v = rmin[mt][h];
            v = fminf(v, __shfl_xor_sync(0xffffffffu, v, 1));
            v = fminf(v, __shfl_xor_sync(0xffffffffu, v, 2));
            if ((lane & 3) == 0) {
                int r = m0w + mt * 16 + (lane >> 2) + h * 8;
                atomicMin(&g_rowmin[rowbase + r], __float_as_uint(v));
            }
        }
}

// ---------------------------------------------------------------------------
// finalize
// ---------------------------------------------------------------------------
__global__ void finalize_kernel(float* __restrict__ out) {
    __shared__ float sl[1024];
    __shared__ float sr[1024];
    int t = threadIdx.x;
    float ls = 0.0f, rs = 0.0f;
    for (int i = t; i < NTOT; i += 1024) {
        float pm = g_posmax[i];
        float nm = __uint_as_float(g_rowmin[i]);
        float pd = (pm > 0.0f) ? sqrtf(pm) : 0.0f;
        float nd = (nm > 0.0f) ? sqrtf(nm) : 0.0f;
        ls += fmaxf(pd - nd + MARGIN, 0.0f);
        rs += g_regpart[i];
    }
    sl[t] = ls; sr[t] = rs;
    __syncthreads();
    #pragma unroll
    for (int s = 512; s; s >>= 1) {
        if (t < s) { sl[t] += sl[t + s]; sr[t] += sr[t + s]; }
        __syncthreads();
    }
    if (t == 0)
        out[0] = sl[0] / (float)NTOT + ALPHA * (sr[0] / (float)(NTOT * DIM));
}

// ---------------------------------------------------------------------------
extern "C" void kernel_launch(void* const* d_in, const int* in_sizes, int n_in,
                              void* d_out, int out_size) {
    const float* a = (const float*)d_in[0];
    const float* p = (const float*)d_in[1];
    const float* n = (const float*)d_in[2];
    float* out = (float*)d_out;

    cudaFuncSetAttribute(tile_kernel,
                         cudaFuncAttributeMaxDynamicSharedMemorySize, SMEM_TOTAL);

    prep_kernel<<<NTOT / 8, 256>>>(a, p, n);
    tile_kernel<<<NTILES * GSPLIT, TPB, SMEM_TOTAL>>>();
    finalize_kernel<<<1, 1024>>>(out);
}

// round 4
// speedup vs baseline: 3.3772x; 2.0689x over previous
#include <cuda_runtime.h>
#include <cuda_bf16.h>
#include <cstdint>
#include <math.h>

// Inputs: a [4096,128] f32, p [4096,128] f32, n [4096,128] f32. Output: 1 f32.

#define B_SIZE 4096
#define DIM    128
#define NTOT   12288
#define NTILES 96
#define TPB    256
#define MARGIN 0.4f
#define ALPHA  0.01f

// ---- smem layout (bytes) ----
#define OFF_SQJ(b)  ((b) * 512)
#define OFF_COLMIN  1024
#define OFF_AHI     2048
#define OFF_ALO     (OFF_AHI + 32768)
#define OFF_BHI(b)  (67584 + (b) * 65536)
#define OFF_BLO(b)  (OFF_BHI(b) + 32768)
#define SMEM_TOTAL  (67584 + 2 * 65536)   // 198656

// ---- device scratch ----
__device__ float          g_sq[NTOT];
__device__ unsigned int   g_rowmin[NTOT];
__device__ float          g_posmax[NTOT];
__device__ float          g_regpart[NTOT];
__device__ __nv_bfloat16  g_hi[NTOT * DIM];
__device__ __nv_bfloat16  g_lo[NTOT * DIM];

// ---- helpers ----
__device__ __forceinline__ uint32_t smem_u32(const void* p) {
    uint32_t a;
    asm("{ .reg .u64 t; cvta.to.shared.u64 t, %1; cvt.u32.u64 %0, t; }"
        : "=r"(a) : "l"(p));
    return a;
}
__device__ __forceinline__ void cp16(uint32_t dst, const void* src) {
    asm volatile("cp.async.cg.shared.global [%0], [%1], 16;"
                 :: "r"(dst), "l"(src));
}
#define CP_COMMIT() asm volatile("cp.async.commit_group;" ::: "memory")
#define CP_WAIT(n)  asm volatile("cp.async.wait_group %0;" :: "n"(n) : "memory")

__device__ __forceinline__ void ldsm4(uint32_t* r, uint32_t addr) {
    asm volatile("ldmatrix.sync.aligned.m8n8.x4.shared.b16 {%0,%1,%2,%3}, [%4];"
                 : "=r"(r[0]), "=r"(r[1]), "=r"(r[2]), "=r"(r[3]) : "r"(addr));
}
__device__ __forceinline__ void mma16816(float* d, const uint32_t* a,
                                         uint32_t b0, uint32_t b1) {
    asm volatile("mma.sync.aligned.m16n8k16.row.col.f32.bf16.bf16.f32 "
                 "{%0,%1,%2,%3}, {%4,%5,%6,%7}, {%8,%9}, {%0,%1,%2,%3};"
                 : "+f"(d[0]), "+f"(d[1]), "+f"(d[2]), "+f"(d[3])
                 : "r"(a[0]), "r"(a[1]), "r"(a[2]), "r"(a[3]),
                   "r"(b0), "r"(b1));
}

__device__ __forceinline__ const float* row_ptr(const float* a, const float* p,
                                                const float* n, int i) {
    if (i < B_SIZE)     return a + (size_t)i * DIM;
    if (i < 2 * B_SIZE) return p + (size_t)(i - B_SIZE) * DIM;
    return n + (size_t)(i - 2 * B_SIZE) * DIM;
}

// ---------------------------------------------------------------------------
// prep: sq / reg / posmax (fp32 exact) + bf16 hi/lo split. One warp per row.
// ---------------------------------------------------------------------------
__global__ void __launch_bounds__(256) prep_kernel(const float* __restrict__ a,
                                                   const float* __restrict__ p,
                                                   const float* __restrict__ n) {
    int gw   = (blockIdx.x * 256 + threadIdx.x) >> 5;
    int lane = threadIdx.x & 31;

    int c = gw & (B_SIZE - 1);
    int p1, p2;
    if (gw < B_SIZE)          { p1 = c + B_SIZE; p2 = c + 2 * B_SIZE; }
    else if (gw < 2 * B_SIZE) { p1 = c;          p2 = c + 2 * B_SIZE; }
    else                      { p1 = c;          p2 = c + B_SIZE;     }

    float4 x  = reinterpret_cast<const float4*>(row_ptr(a, p, n, gw))[lane];
    float4 y1 = reinterpret_cast<const float4*>(row_ptr(a, p, n, p1))[lane];
    float4 y2 = reinterpret_cast<const float4*>(row_ptr(a, p, n, p2))[lane];

    float xs[4]  = {x.x, x.y, x.z, x.w};
    float y1s[4] = {y1.x, y1.y, y1.z, y1.w};
    float y2s[4] = {y2.x, y2.y, y2.z, y2.w};

    float sq = 0.f, reg = 0.f, e1 = 0.f, e2 = 0.f;
    #pragma unroll
    for (int i = 0; i < 4; i++) {
        sq += xs[i] * xs[i];
        float ax = fabsf(xs[i]) - 1.0f;
        reg += ax * ax;
        float d1 = xs[i] - y1s[i]; e1 += d1 * d1;
        float d2 = xs[i] - y2s[i]; e2 += d2 * d2;
    }
    #pragma unroll
    for (int ofs = 16; ofs; ofs >>= 1) {
        sq  += __shfl_xor_sync(0xffffffffu, sq,  ofs);
        reg += __shfl_xor_sync(0xffffffffu, reg, ofs);
        e1  += __shfl_xor_sync(0xffffffffu, e1,  ofs);
        e2  += __shfl_xor_sync(0xffffffffu, e2,  ofs);
    }
    if (lane == 0) {
        g_sq[gw]      = sq;
        g_regpart[gw] = reg;
        g_posmax[gw]  = fmaxf(e1, e2);
        g_rowmin[gw]  = 0x7f800000u;   // +inf bits
    }

    unsigned hu0 = 0, hu1 = 0, lu0 = 0, lu1 = 0;
    #pragma unroll
    for (int i = 0; i < 4; i++) {
        __nv_bfloat16 h = __float2bfloat16(xs[i]);
        __nv_bfloat16 l = __float2bfloat16(xs[i] - __bfloat162float(h));
        unsigned hb = __bfloat16_as_ushort(h);
        unsigned lb = __bfloat16_as_ushort(l);
        if (i < 2) { hu0 |= hb << (16 * i);       lu0 |= lb << (16 * i); }
        else       { hu1 |= hb << (16 * (i - 2)); lu1 |= lb << (16 * (i - 2)); }
    }
    reinterpret_cast<uint2*>(g_hi)[gw * 32 + lane] = make_uint2(hu0, hu1);
    reinterpret_cast<uint2*>(g_lo)[gw * 32 + lane] = make_uint2(lu0, lu1);
}

// ---------------------------------------------------------------------------
// prefetch one 128x128 bf16 tile (32KB) global -> swizzled smem via cp.async.
// ---------------------------------------------------------------------------
__device__ __forceinline__ void prefetch_tile(const __nv_bfloat16* __restrict__ g,
                                              int rowbase, uint32_t sm_off,
                                              uint32_t sb, int tid) {
    const uint4* src = reinterpret_cast<const uint4*>(g) + (size_t)rowbase * 16;
    #pragma unroll
    for (int i = 0; i < 8; i++) {
        int ch = tid + i * 256;
        int m = ch >> 4, c = ch & 15;
        uint32_t dst = sb + sm_off + ((uint32_t)m << 8) + ((uint32_t)(c ^ (m & 7)) << 4);
        cp16(dst, src + ch);
    }
}

// ---------------------------------------------------------------------------
// tile kernel: symmetric coverage via cyclic offsets.
// CTA = (row tile bi, delta-group g). Tiles: bj = (bi + 16g + t) % 96,
// t in [0, ntl) with ntl = 16 (+1 for g==2 && bi<48, covering delta=48).
// Each tile updates row-mins (registers) AND col-mins (smem -> global).
// ---------------------------------------------------------------------------
__global__ void __launch_bounds__(TPB, 1) tile_kernel() {
    extern __shared__ char smem[];
    uint32_t sb = smem_u32(smem);
    const int tid  = threadIdx.x;
    const int wid  = tid >> 5;
    const int lane = tid & 31;

    const int bi   = blockIdx.x / 3;
    const int grp  = blockIdx.x % 3;
    const int d0   = grp * 16;
    const int ntl  = 16 + ((grp == 2 && bi < 48) ? 1 : 0);
    const int rowbase = bi * 128;

    // warp layout: 2 warps in M (64 rows each) x 4 warps in N (32 cols each)
    const int wy  = wid & 1,  wx = wid >> 1;
    const int m0w = wy * 64,  n0w = wx * 32;

    // initial prefetch: A tiles + B tile 0 + sqj0
    const int bj0 = (bi + d0) % NTILES;
    prefetch_tile(g_hi, rowbase, OFF_AHI, sb, tid);
    prefetch_tile(g_lo, rowbase, OFF_ALO, sb, tid);
    prefetch_tile(g_hi, bj0 * 128, OFF_BHI(0), sb, tid);
    prefetch_tile(g_lo, bj0 * 128, OFF_BLO(0), sb, tid);
    if (tid < 32) cp16(sb + OFF_SQJ(0) + tid * 16, g_sq + bj0 * 128 + tid * 4);
    CP_COMMIT();

    // init col-min buffer
    unsigned int* colmin = reinterpret_cast<unsigned int*>(smem + OFF_COLMIN);
    if (tid < 128) colmin[tid] = 0x7f800000u;

    float sqi[4][2];
    float rmin[4][2];
    #pragma unroll
    for (int mt = 0; mt < 4; mt++)
        #pragma unroll
        for (int h = 0; h < 2; h++) {
            int r = m0w + mt * 16 + (lane >> 2) + h * 8;
            sqi[mt][h]  = g_sq[rowbase + r];
            rmin[mt][h] = __int_as_float(0x7f800000);
        }

    const int a_rbit = (lane >> 3) & 1;
    const int a_cbit = (lane >> 4) & 1;
    const int b_rbit = (lane >> 4) & 1;
    const int b_cbit = (lane >> 3) & 1;
    const int l7 = lane & 7;

    for (int t = 0; t < ntl; t++) {
        const int b  = t & 1, nb = b ^ 1;
        const int jt = (bi + d0 + t) % NTILES;

        if (t + 1 < ntl) {
            const int jn = (bi + d0 + t + 1) % NTILES;
            prefetch_tile(g_hi, jn * 128, OFF_BHI(nb), sb, tid);
            prefetch_tile(g_lo, jn * 128, OFF_BLO(nb), sb, tid);
            if (tid < 32)
                cp16(sb + OFF_SQJ(nb) + tid * 16, g_sq + jn * 128 + tid * 4);
            CP_COMMIT();
            CP_WAIT(1);
        } else {
            CP_WAIT(0);
        }
        __syncthreads();   // B buf b + sqj(b) ready, colmin initialized

        // ---- MMA: per k-step, load all fragments once, 3 products ----
        float acc[4][4][4];
        #pragma unroll
        for (int mt = 0; mt < 4; mt++)
            #pragma unroll
            for (int nt = 0; nt < 4; nt++)
                #pragma unroll
                for (int k = 0; k < 4; k++) acc[mt][nt][k] = 0.0f;

        const uint32_t AbH = sb + OFF_AHI, AbL = sb + OFF_ALO;
        const uint32_t BbH = sb + OFF_BHI(b), BbL = sb + OFF_BLO(b);

        #pragma unroll
        for (int ks = 0; ks < 8; ks++) {
            const int c0 = ks * 2;
            uint32_t afh[4][4], afl[4][4], bfh[2][4], bfl[2][4];
            #pragma unroll
            for (int mt = 0; mt < 4; mt++) {
                int row = m0w + mt * 16 + l7 + a_rbit * 8;
                uint32_t o = ((uint32_t)row << 8) +
                             ((uint32_t)((c0 + a_cbit) ^ (row & 7)) << 4);
                ldsm4(afh[mt], AbH + o);
                ldsm4(afl[mt], AbL + o);
            }
            #pragma unroll
            for (int bt = 0; bt < 2; bt++) {
                int row = n0w + bt * 16 + l7 + b_rbit * 8;
                uint32_t o = ((uint32_t)row << 8) +
                             ((uint32_t)((c0 + b_cbit) ^ (row & 7)) << 4);
                ldsm4(bfh[bt], BbH + o);
                ldsm4(bfl[bt], BbL + o);
            }
            #pragma unroll
            for (int mt = 0; mt < 4; mt++)
                #pragma unroll
                for (int nt = 0; nt < 4; nt++) {
                    uint32_t bh0 = bfh[nt >> 1][(nt & 1) * 2];
                    uint32_t bh1 = bfh[nt >> 1][(nt & 1) * 2 + 1];
                    uint32_t bl0 = bfl[nt >> 1][(nt & 1) * 2];
                    uint32_t bl1 = bfl[nt >> 1][(nt & 1) * 2 + 1];
                    mma16816(acc[mt][nt], afh[mt], bh0, bh1);   // Hi*Hi
                    mma16816(acc[mt][nt], afh[mt], bl0, bl1);   // Hi*Lo
                    mma16816(acc[mt][nt], afl[mt], bh0, bh1);   // Lo*Hi
                }
        }

        // ---- epilogue: d^2, mask, row-min regs + col-min regs ----
        const float* sqj = reinterpret_cast<const float*>(smem + OFF_SQJ(b));
        const bool diag = ((bi & 31) == (jt & 31));
        const float FINF = __int_as_float(0x7f800000);

        float cmin[4][2];
        #pragma unroll
        for (int nt = 0; nt < 4; nt++) { cmin[nt][0] = FINF; cmin[nt][1] = FINF; }

        #pragma unroll
        for (int mt = 0; mt < 4; mt++) {
            const int r0 = m0w + mt * 16 + (lane >> 2);
            const int r1 = r0 + 8;
            #pragma unroll
            for (int nt = 0; nt < 4; nt++) {
                const int c0i = n0w + nt * 8 + (lane & 3) * 2;
                float2 sj = *reinterpret_cast<const float2*>(&sqj[c0i]);
                float d00 = fmaxf(fmaf(acc[mt][nt][0], -2.f, sqi[mt][0] + sj.x), 0.f);
                float d01 = fmaxf(fmaf(acc[mt][nt][1], -2.f, sqi[mt][0] + sj.y), 0.f);
                float d10 = fmaxf(fmaf(acc[mt][nt][2], -2.f, sqi[mt][1] + sj.x), 0.f);
                float d11 = fmaxf(fmaf(acc[mt][nt][3], -2.f, sqi[mt][1] + sj.y), 0.f);
                if (diag) {
                    if (r0 == c0i)     d00 = FINF;
                    if (r0 == c0i + 1) d01 = FINF;
                    if (r1 == c0i)     d10 = FINF;
                    if (r1 == c0i + 1) d11 = FINF;
                }
                rmin[mt][0] = fminf(rmin[mt][0], fminf(d00, d01));
                rmin[mt][1] = fminf(rmin[mt][1], fminf(d10, d11));
                cmin[nt][0] = fminf(cmin[nt][0], fminf(d00, d10));
                cmin[nt][1] = fminf(cmin[nt][1], fminf(d01, d11));
            }
        }

        // fold col-mins across the 8 row-groups in this warp (lane>>2)
        #pragma unroll
        for (int nt = 0; nt < 4; nt++)
            #pragma unroll
            for (int h = 0; h < 2; h++) {
                float v = cmin[nt][h];
                v = fminf(v, __shfl_xor_sync(0xffffffffu, v, 4));
                v = fminf(v, __shfl_xor_sync(0xffffffffu, v, 8));
                v = fminf(v, __shfl_xor_sync(0xffffffffu, v, 16));
                cmin[nt][h] = v;
            }
        if (lane < 4) {
            #pragma unroll
            for (int nt = 0; nt < 4; nt++) {
                int c = n0w + nt * 8 + lane * 2;
                atomicMin(&colmin[c],     __float_as_uint(cmin[nt][0]));
                atomicMin(&colmin[c + 1], __float_as_uint(cmin[nt][1]));
            }
        }
        __syncthreads();   // colmin complete; everyone done with buf b

        if (tid < 128) {
            atomicMin(&g_rowmin[jt * 128 + tid], colmin[tid]);
            colmin[tid] = 0x7f800000u;   // re-init for next tile
        }
        // (next iteration's top __syncthreads orders re-init vs. new atomics)
    }

    // ---- final row-min: lanes sharing a row, then global atomic ----
    #pragma unroll
    for (int mt = 0; mt < 4; mt++)
        #pragma unroll
        for (int h = 0; h < 2; h++) {
            float v = rmin[mt][h];
            v = fminf(v, __shfl_xor_sync(0xffffffffu, v, 1));
            v = fminf(v, __shfl_xor_sync(0xffffffffu, v, 2));
            if ((lane & 3) == 0) {
                int r = m0w + mt * 16 + (lane >> 2) + h * 8;
                atomicMin(&g_rowmin[rowbase + r], __float_as_uint(v));
            }
        }
}

// ---------------------------------------------------------------------------
// finalize
// ---------------------------------------------------------------------------
__global__ void finalize_kernel(float* __restrict__ out) {
    __shared__ float sl[1024];
    __shared__ float sr[1024];
    int t = threadIdx.x;
    float ls = 0.0f, rs = 0.0f;
    for (int i = t; i < NTOT; i += 1024) {
        float pm = g_posmax[i];
        float nm = __uint_as_float(g_rowmin[i]);
        float pd = (pm > 0.0f) ? sqrtf(pm) : 0.0f;
        float nd = (nm > 0.0f) ? sqrtf(nm) : 0.0f;
        ls += fmaxf(pd - nd + MARGIN, 0.0f);
        rs += g_regpart[i];
    }
    sl[t] = ls; sr[t] = rs;
    __syncthreads();
    #pragma unroll
    for (int s = 512; s; s >>= 1) {
        if (t < s) { sl[t] += sl[t + s]; sr[t] += sr[t + s]; }
        __syncthreads();
    }
    if (t == 0)
        out[0] = sl[0] / (float)NTOT + ALPHA * (sr[0] / (float)(NTOT * DIM));
}

// ---------------------------------------------------------------------------
extern "C" void kernel_launch(void* const* d_in, const int* in_sizes, int n_in,
                              void* d_out, int out_size) {
    const float* a = (const float*)d_in[0];
    const float* p = (const float*)d_in[1];
    const float* n = (const float*)d_in[2];
    float* out = (float*)d_out;

    cudaFuncSetAttribute(tile_kernel,
                         cudaFuncAttributeMaxDynamicSharedMemorySize, SMEM_TOTAL);

    prep_kernel<<<NTOT / 8, 256>>>(a, p, n);
    tile_kernel<<<NTILES * 3, TPB, SMEM_TOTAL>>>();
    finalize_kernel<<<1, 1024>>>(out);
}

// round 5
// speedup vs baseline: 6.9916x; 2.0702x over previous
#include <cuda_runtime.h>
#include <cuda_fp16.h>
#include <cstdint>
#include <math.h>

// Inputs: a [4096,128] f32, p [4096,128] f32, n [4096,128] f32. Output: 1 f32.

#define B_SIZE 4096
#define DIM    128
#define NTOT   12288
#define NTILES 96
#define TPB    256
#define MARGIN 0.4f
#define ALPHA  0.01f

// ---- smem layout (bytes) ----
#define OFF_SQJ(b)  ((b) * 512)
#define OFF_COLMIN  1024
#define OFF_A       2048
#define OFF_B(b)    (OFF_A + 32768 + (b) * 32768)
#define SMEM_TOTAL  (OFF_A + 32768 + 2 * 32768)   // 100352

// ---- device scratch ----
__device__ float         g_sq[NTOT];
__device__ unsigned int  g_rowmin[NTOT];
__device__ float         g_posmax[NTOT];
__device__ float         g_regpart[NTOT];
__device__ __half        g_h[NTOT * DIM];

// ---- helpers ----
__device__ __forceinline__ uint32_t smem_u32(const void* p) {
    uint32_t a;
    asm("{ .reg .u64 t; cvta.to.shared.u64 t, %1; cvt.u32.u64 %0, t; }"
        : "=r"(a) : "l"(p));
    return a;
}
__device__ __forceinline__ void cp16(uint32_t dst, const void* src) {
    asm volatile("cp.async.cg.shared.global [%0], [%1], 16;"
                 :: "r"(dst), "l"(src));
}
#define CP_COMMIT() asm volatile("cp.async.commit_group;" ::: "memory")
#define CP_WAIT(n)  asm volatile("cp.async.wait_group %0;" :: "n"(n) : "memory")

__device__ __forceinline__ void ldsm4(uint32_t* r, uint32_t addr) {
    asm volatile("ldmatrix.sync.aligned.m8n8.x4.shared.b16 {%0,%1,%2,%3}, [%4];"
                 : "=r"(r[0]), "=r"(r[1]), "=r"(r[2]), "=r"(r[3]) : "r"(addr));
}
__device__ __forceinline__ void mma16816(float* d, const uint32_t* a,
                                         uint32_t b0, uint32_t b1) {
    asm volatile("mma.sync.aligned.m16n8k16.row.col.f32.f16.f16.f32 "
                 "{%0,%1,%2,%3}, {%4,%5,%6,%7}, {%8,%9}, {%0,%1,%2,%3};"
                 : "+f"(d[0]), "+f"(d[1]), "+f"(d[2]), "+f"(d[3])
                 : "r"(a[0]), "r"(a[1]), "r"(a[2]), "r"(a[3]),
                   "r"(b0), "r"(b1));
}

__device__ __forceinline__ const float* row_ptr(const float* a, const float* p,
                                                const float* n, int i) {
    if (i < B_SIZE)     return a + (size_t)i * DIM;
    if (i < 2 * B_SIZE) return p + (size_t)(i - B_SIZE) * DIM;
    return n + (size_t)(i - 2 * B_SIZE) * DIM;
}

// ---------------------------------------------------------------------------
// prep: sq / reg / posmax (fp32 exact) + fp16 conversion. One warp per row.
// ---------------------------------------------------------------------------
__global__ void __launch_bounds__(256) prep_kernel(const float* __restrict__ a,
                                                   const float* __restrict__ p,
                                                   const float* __restrict__ n) {
    int gw   = (blockIdx.x * 256 + threadIdx.x) >> 5;
    int lane = threadIdx.x & 31;

    int c = gw & (B_SIZE - 1);
    int p1, p2;
    if (gw < B_SIZE)          { p1 = c + B_SIZE; p2 = c + 2 * B_SIZE; }
    else if (gw < 2 * B_SIZE) { p1 = c;          p2 = c + 2 * B_SIZE; }
    else                      { p1 = c;          p2 = c + B_SIZE;     }

    float4 x  = reinterpret_cast<const float4*>(row_ptr(a, p, n, gw))[lane];
    float4 y1 = reinterpret_cast<const float4*>(row_ptr(a, p, n, p1))[lane];
    float4 y2 = reinterpret_cast<const float4*>(row_ptr(a, p, n, p2))[lane];

    float xs[4]  = {x.x, x.y, x.z, x.w};
    float y1s[4] = {y1.x, y1.y, y1.z, y1.w};
    float y2s[4] = {y2.x, y2.y, y2.z, y2.w};

    float sq = 0.f, reg = 0.f, e1 = 0.f, e2 = 0.f;
    #pragma unroll
    for (int i = 0; i < 4; i++) {
        sq += xs[i] * xs[i];
        float ax = fabsf(xs[i]) - 1.0f;
        reg += ax * ax;
        float d1 = xs[i] - y1s[i]; e1 += d1 * d1;
        float d2 = xs[i] - y2s[i]; e2 += d2 * d2;
    }
    #pragma unroll
    for (int ofs = 16; ofs; ofs >>= 1) {
        sq  += __shfl_xor_sync(0xffffffffu, sq,  ofs);
        reg += __shfl_xor_sync(0xffffffffu, reg, ofs);
        e1  += __shfl_xor_sync(0xffffffffu, e1,  ofs);
        e2  += __shfl_xor_sync(0xffffffffu, e2,  ofs);
    }
    if (lane == 0) {
        g_sq[gw]      = sq;
        g_regpart[gw] = reg;
        g_posmax[gw]  = fmaxf(e1, e2);
        g_rowmin[gw]  = 0x7f800000u;   // +inf bits
    }

    unsigned h0 = 0, h1 = 0;
    #pragma unroll
    for (int i = 0; i < 4; i++) {
        unsigned hb = __half_as_ushort(__float2half_rn(xs[i]));
        if (i < 2) h0 |= hb << (16 * i);
        else       h1 |= hb << (16 * (i - 2));
    }
    reinterpret_cast<uint2*>(g_h)[gw * 32 + lane] = make_uint2(h0, h1);
}

// ---------------------------------------------------------------------------
// prefetch one 128x128 fp16 tile (32KB) global -> swizzled smem via cp.async.
// ---------------------------------------------------------------------------
__device__ __forceinline__ void prefetch_tile(const __half* __restrict__ g,
                                              int rowbase, uint32_t sm_off,
                                              uint32_t sb, int tid) {
    const uint4* src = reinterpret_cast<const uint4*>(g) + (size_t)rowbase * 16;
    #pragma unroll
    for (int i = 0; i < 8; i++) {
        int ch = tid + i * 256;
        int m = ch >> 4, c = ch & 15;
        uint32_t dst = sb + sm_off + ((uint32_t)m << 8) + ((uint32_t)(c ^ (m & 7)) << 4);
        cp16(dst, src + ch);
    }
}

// ---------------------------------------------------------------------------
// tile kernel: symmetric coverage via cyclic offsets, fp16 single product.
// CTA = (row tile bi, delta-group g). Tiles: bj = (bi + 16g + t) % 96,
// t in [0, ntl) with ntl = 16 (+1 for g==2 && bi<48, covering delta=48).
// ---------------------------------------------------------------------------
__global__ void __launch_bounds__(TPB, 2) tile_kernel() {
    extern __shared__ char smem[];
    uint32_t sb = smem_u32(smem);
    const int tid  = threadIdx.x;
    const int wid  = tid >> 5;
    const int lane = tid & 31;

    const int bi   = blockIdx.x / 3;
    const int grp  = blockIdx.x % 3;
    const int d0   = grp * 16;
    const int ntl  = 16 + ((grp == 2 && bi < 48) ? 1 : 0);
    const int rowbase = bi * 128;

    // warp layout: 2 warps in M (64 rows each) x 4 warps in N (32 cols each)
    const int wy  = wid & 1,  wx = wid >> 1;
    const int m0w = wy * 64,  n0w = wx * 32;

    const int bj0 = (bi + d0) % NTILES;
    prefetch_tile(g_h, rowbase, OFF_A, sb, tid);
    prefetch_tile(g_h, bj0 * 128, OFF_B(0), sb, tid);
    if (tid < 32) cp16(sb + OFF_SQJ(0) + tid * 16, g_sq + bj0 * 128 + tid * 4);
    CP_COMMIT();

    unsigned int* colmin = reinterpret_cast<unsigned int*>(smem + OFF_COLMIN);
    if (tid < 128) colmin[tid] = 0x7f800000u;

    float sqi[4][2];
    float rmin[4][2];
    #pragma unroll
    for (int mt = 0; mt < 4; mt++)
        #pragma unroll
        for (int h = 0; h < 2; h++) {
            int r = m0w + mt * 16 + (lane >> 2) + h * 8;
            sqi[mt][h]  = g_sq[rowbase + r];
            rmin[mt][h] = __int_as_float(0x7f800000);
        }

    const int a_rbit = (lane >> 3) & 1;
    const int a_cbit = (lane >> 4) & 1;
    const int b_rbit = (lane >> 4) & 1;
    const int b_cbit = (lane >> 3) & 1;
    const int l7 = lane & 7;

    for (int t = 0; t < ntl; t++) {
        const int b  = t & 1, nb = b ^ 1;
        const int jt = (bi + d0 + t) % NTILES;

        if (t + 1 < ntl) {
            const int jn = (bi + d0 + t + 1) % NTILES;
            prefetch_tile(g_h, jn * 128, OFF_B(nb), sb, tid);
            if (tid < 32)
                cp16(sb + OFF_SQJ(nb) + tid * 16, g_sq + jn * 128 + tid * 4);
            CP_COMMIT();
            CP_WAIT(1);
        } else {
            CP_WAIT(0);
        }
        __syncthreads();   // B buf b + sqj(b) ready, colmin ready

        // ---- MMA: single fp16 product, K=128 ----
        float acc[4][4][4];
        #pragma unroll
        for (int mt = 0; mt < 4; mt++)
            #pragma unroll
            for (int nt = 0; nt < 4; nt++)
                #pragma unroll
                for (int k = 0; k < 4; k++) acc[mt][nt][k] = 0.0f;

        const uint32_t Ab = sb + OFF_A, Bb = sb + OFF_B(b);

        #pragma unroll
        for (int ks = 0; ks < 8; ks++) {
            const int c0 = ks * 2;
            uint32_t af[4][4], bf[2][4];
            #pragma unroll
            for (int mt = 0; mt < 4; mt++) {
                int row = m0w + mt * 16 + l7 + a_rbit * 8;
                ldsm4(af[mt], Ab + ((uint32_t)row << 8) +
                              ((uint32_t)((c0 + a_cbit) ^ (row & 7)) << 4));
            }
            #pragma unroll
            for (int bt = 0; bt < 2; bt++) {
                int row = n0w + bt * 16 + l7 + b_rbit * 8;
                ldsm4(bf[bt], Bb + ((uint32_t)row << 8) +
                              ((uint32_t)((c0 + b_cbit) ^ (row & 7)) << 4));
            }
            #pragma unroll
            for (int mt = 0; mt < 4; mt++)
                #pragma unroll
                for (int nt = 0; nt < 4; nt++)
                    mma16816(acc[mt][nt], af[mt],
                             bf[nt >> 1][(nt & 1) * 2],
                             bf[nt >> 1][(nt & 1) * 2 + 1]);
        }

        // ---- epilogue: d^2, mask, row-min regs + col-min ----
        const float* sqj = reinterpret_cast<const float*>(smem + OFF_SQJ(b));
        const bool diag = ((bi & 31) == (jt & 31));
        const float FINF = __int_as_float(0x7f800000);

        float cmin[4][2];
        #pragma unroll
        for (int nt = 0; nt < 4; nt++) { cmin[nt][0] = FINF; cmin[nt][1] = FINF; }

        #pragma unroll
        for (int mt = 0; mt < 4; mt++) {
            const int r0 = m0w + mt * 16 + (lane >> 2);
            const int r1 = r0 + 8;
            #pragma unroll
            for (int nt = 0; nt < 4; nt++) {
                const int c0i = n0w + nt * 8 + (lane & 3) * 2;
                float2 sj = *reinterpret_cast<const float2*>(&sqj[c0i]);
                float d00 = fmaxf(fmaf(acc[mt][nt][0], -2.f, sqi[mt][0] + sj.x), 0.f);
                float d01 = fmaxf(fmaf(acc[mt][nt][1], -2.f, sqi[mt][0] + sj.y), 0.f);
                float d10 = fmaxf(fmaf(acc[mt][nt][2], -2.f, sqi[mt][1] + sj.x), 0.f);
                float d11 = fmaxf(fmaf(acc[mt][nt][3], -2.f, sqi[mt][1] + sj.y), 0.f);
                if (diag) {
                    if (r0 == c0i)     d00 = FINF;
                    if (r0 == c0i + 1) d01 = FINF;
                    if (r1 == c0i)     d10 = FINF;
                    if (r1 == c0i + 1) d11 = FINF;
                }
                rmin[mt][0] = fminf(rmin[mt][0], fminf(d00, d01));
                rmin[mt][1] = fminf(rmin[mt][1], fminf(d10, d11));
                cmin[nt][0] = fminf(cmin[nt][0], fminf(d00, d10));
                cmin[nt][1] = fminf(cmin[nt][1], fminf(d01, d11));
            }
        }

        #pragma unroll
        for (int nt = 0; nt < 4; nt++)
            #pragma unroll
            for (int h = 0; h < 2; h++) {
                float v = cmin[nt][h];
                v = fminf(v, __shfl_xor_sync(0xffffffffu, v, 4));
                v = fminf(v, __shfl_xor_sync(0xffffffffu, v, 8));
                v = fminf(v, __shfl_xor_sync(0xffffffffu, v, 16));
                cmin[nt][h] = v;
            }
        if (lane < 4) {
            #pragma unroll
            for (int nt = 0; nt < 4; nt++) {
                int c = n0w + nt * 8 + lane * 2;
                atomicMin(&colmin[c],     __float_as_uint(cmin[nt][0]));
                atomicMin(&colmin[c + 1], __float_as_uint(cmin[nt][1]));
            }
        }
        __syncthreads();   // colmin complete; everyone done with buf b

        if (tid < 128) {
            atomicMin(&g_rowmin[jt * 128 + tid], colmin[tid]);
            colmin[tid] = 0x7f800000u;   // re-init for next tile
        }
    }

    // ---- final row-min: lanes sharing a row, then global atomic ----
    #pragma unroll
    for (int mt = 0; mt < 4; mt++)
        #pragma unroll
        for (int h = 0; h < 2; h++) {
            float v = rmin[mt][h];
            v = fminf(v, __shfl_xor_sync(0xffffffffu, v, 1));
            v = fminf(v, __shfl_xor_sync(0xffffffffu, v, 2));
            if ((lane & 3) == 0) {
                int r = m0w + mt * 16 + (lane >> 2) + h * 8;
                atomicMin(&g_rowmin[rowbase + r], __float_as_uint(v));
            }
        }
}

// ---------------------------------------------------------------------------
// finalize
// ---------------------------------------------------------------------------
__global__ void finalize_kernel(float* __restrict__ out) {
    __shared__ float sl[1024];
    __shared__ float sr[1024];
    int t = threadIdx.x;
    float ls = 0.0f, rs = 0.0f;
    for (int i = t; i < NTOT; i += 1024) {
        float pm = g_posmax[i];
        float nm = __uint_as_float(g_rowmin[i]);
        float pd = (pm > 0.0f) ? sqrtf(pm) : 0.0f;
        float nd = (nm > 0.0f) ? sqrtf(nm) : 0.0f;
        ls += fmaxf(pd - nd + MARGIN, 0.0f);
        rs += g_regpart[i];
    }
    sl[t] = ls; sr[t] = rs;
    __syncthreads();
    #pragma unroll
    for (int s = 512; s; s >>= 1) {
        if (t < s) { sl[t] += sl[t + s]; sr[t] += sr[t + s]; }
        __syncthreads();
    }
    if (t == 0)
        out[0] = sl[0] / (float)NTOT + ALPHA * (sr[0] / (float)(NTOT * DIM));
}

// ---------------------------------------------------------------------------
extern "C" void kernel_launch(void* const* d_in, const int* in_sizes, int n_in,
                              void* d_out, int out_size) {
    const float* a = (const float*)d_in[0];
    const float* p = (const float*)d_in[1];
    const float* n = (const float*)d_in[2];
    float* out = (float*)d_out;

    cudaFuncSetAttribute(tile_kernel,
                         cudaFuncAttributeMaxDynamicSharedMemorySize, SMEM_TOTAL);

    prep_kernel<<<NTOT / 8, 256>>>(a, p, n);
    tile_kernel<<<NTILES * 3, TPB, SMEM_TOTAL>>>();
    finalize_kernel<<<1, 1024>>>(out);
}

// round 6
// speedup vs baseline: 7.0447x; 1.0076x over previous
#include <cuda_runtime.h>
#include <cuda_fp16.h>
#include <cstdint>
#include <math.h>

// Inputs: a [4096,128] f32, p [4096,128] f32, n [4096,128] f32. Output: 1 f32.

#define B_SIZE 4096
#define DIM    128
#define NTOT   12288
#define NTILES 96
#define TPB    256
#define MARGIN 0.4f
#define ALPHA  0.01f

// ---- smem layout (bytes) ----
#define OFF_SQJ(b)  ((b) * 512)
#define OFF_COLMIN  1024
#define OFF_A       2048
#define OFF_B(b)    (OFF_A + 32768 + (b) * 32768)
#define SMEM_TOTAL  (OFF_A + 32768 + 2 * 32768)   // 100352

// ---- device scratch ----
__device__ float         g_sq[NTOT];
__device__ unsigned int  g_rowmin[NTOT];
__device__ float         g_posmax[NTOT];
__device__ float         g_regpart[NTOT];
__device__ __half        g_h[NTOT * DIM];

// ---- helpers ----
__device__ __forceinline__ uint32_t smem_u32(const void* p) {
    uint32_t a;
    asm("{ .reg .u64 t; cvta.to.shared.u64 t, %1; cvt.u32.u64 %0, t; }"
        : "=r"(a) : "l"(p));
    return a;
}
__device__ __forceinline__ void cp16(uint32_t dst, const void* src) {
    asm volatile("cp.async.cg.shared.global [%0], [%1], 16;"
                 :: "r"(dst), "l"(src));
}
#define CP_COMMIT() asm volatile("cp.async.commit_group;" ::: "memory")
#define CP_WAIT(n)  asm volatile("cp.async.wait_group %0;" :: "n"(n) : "memory")

__device__ __forceinline__ void ldsm4(uint32_t* r, uint32_t addr) {
    asm volatile("ldmatrix.sync.aligned.m8n8.x4.shared.b16 {%0,%1,%2,%3}, [%4];"
                 : "=r"(r[0]), "=r"(r[1]), "=r"(r[2]), "=r"(r[3]) : "r"(addr));
}
// fp16 accumulate variant: 2x rate on the legacy tensor path
__device__ __forceinline__ void mma16816h(uint32_t* d, const uint32_t* a,
                                          uint32_t b0, uint32_t b1) {
    asm volatile("mma.sync.aligned.m16n8k16.row.col.f16.f16.f16.f16 "
                 "{%0,%1}, {%2,%3,%4,%5}, {%6,%7}, {%0,%1};"
                 : "+r"(d[0]), "+r"(d[1])
                 : "r"(a[0]), "r"(a[1]), "r"(a[2]), "r"(a[3]),
                   "r"(b0), "r"(b1));
}

// ---------------------------------------------------------------------------
// prep: one warp per column index c. Loads a_c, p_c, n_c ONCE, produces
// sq/reg/posmax/rowmin-init for all three rows + fp16 conversions.
// ---------------------------------------------------------------------------
__global__ void __launch_bounds__(256) prep_kernel(const float* __restrict__ a,
                                                   const float* __restrict__ p,
                                                   const float* __restrict__ n) {
    int c    = (blockIdx.x * 256 + threadIdx.x) >> 5;   // 0..4095
    int lane = threadIdx.x & 31;

    float4 xa = reinterpret_cast<const float4*>(a + (size_t)c * DIM)[lane];
    float4 xp = reinterpret_cast<const float4*>(p + (size_t)c * DIM)[lane];
    float4 xn = reinterpret_cast<const float4*>(n + (size_t)c * DIM)[lane];

    float as[4] = {xa.x, xa.y, xa.z, xa.w};
    float ps[4] = {xp.x, xp.y, xp.z, xp.w};
    float ns[4] = {xn.x, xn.y, xn.z, xn.w};

    float sqa = 0.f, sqp = 0.f, sqn = 0.f;
    float ra = 0.f, rp = 0.f, rn = 0.f;
    float eap = 0.f, ean = 0.f, epn = 0.f;
    #pragma unroll
    for (int i = 0; i < 4; i++) {
        sqa += as[i] * as[i];  sqp += ps[i] * ps[i];  sqn += ns[i] * ns[i];
        float ta = fabsf(as[i]) - 1.f; ra += ta * ta;
        float tp = fabsf(ps[i]) - 1.f; rp += tp * tp;
        float tn = fabsf(ns[i]) - 1.f; rn += tn * tn;
        float d1 = as[i] - ps[i]; eap += d1 * d1;
        float d2 = as[i] - ns[i]; ean += d2 * d2;
        float d3 = ps[i] - ns[i]; epn += d3 * d3;
    }
    #pragma unroll
    for (int ofs = 16; ofs; ofs >>= 1) {
        sqa += __shfl_xor_sync(0xffffffffu, sqa, ofs);
        sqp += __shfl_xor_sync(0xffffffffu, sqp, ofs);
        sqn += __shfl_xor_sync(0xffffffffu, sqn, ofs);
        ra  += __shfl_xor_sync(0xffffffffu, ra,  ofs);
        rp  += __shfl_xor_sync(0xffffffffu, rp,  ofs);
        rn  += __shfl_xor_sync(0xffffffffu, rn,  ofs);
        eap += __shfl_xor_sync(0xffffffffu, eap, ofs);
        ean += __shfl_xor_sync(0xffffffffu, ean, ofs);
        epn += __shfl_xor_sync(0xffffffffu, epn, ofs);
    }
    if (lane == 0) {
        g_sq[c]                = sqa;
        g_sq[c + B_SIZE]       = sqp;
        g_sq[c + 2 * B_SIZE]   = sqn;
        g_regpart[c]               = ra;
        g_regpart[c + B_SIZE]      = rp;
        g_regpart[c + 2 * B_SIZE]  = rn;
        g_posmax[c]                = fmaxf(eap, ean);
        g_posmax[c + B_SIZE]       = fmaxf(eap, epn);
        g_posmax[c + 2 * B_SIZE]   = fmaxf(ean, epn);
        g_rowmin[c]                = 0x7f800000u;
        g_rowmin[c + B_SIZE]       = 0x7f800000u;
        g_rowmin[c + 2 * B_SIZE]   = 0x7f800000u;
    }

    // fp16 conversions (packed 8B per lane per row)
    #pragma unroll
    for (int seg = 0; seg < 3; seg++) {
        const float* s = (seg == 0) ? as : (seg == 1) ? ps : ns;
        unsigned h0 = 0, h1 = 0;
        #pragma unroll
        for (int i = 0; i < 4; i++) {
            unsigned hb = __half_as_ushort(__float2half_rn(s[i]));
            if (i < 2) h0 |= hb << (16 * i);
            else       h1 |= hb << (16 * (i - 2));
        }
        reinterpret_cast<uint2*>(g_h)[(c + seg * B_SIZE) * 32 + lane] =
            make_uint2(h0, h1);
    }
}

// ---------------------------------------------------------------------------
// prefetch one 128x128 fp16 tile (32KB) global -> swizzled smem via cp.async.
// ---------------------------------------------------------------------------
__device__ __forceinline__ void prefetch_tile(const __half* __restrict__ g,
                                              int rowbase, uint32_t sm_off,
                                              uint32_t sb, int tid) {
    const uint4* src = reinterpret_cast<const uint4*>(g) + (size_t)rowbase * 16;
    #pragma unroll
    for (int i = 0; i < 8; i++) {
        int ch = tid + i * 256;
        int m = ch >> 4, c = ch & 15;
        uint32_t dst = sb + sm_off + ((uint32_t)m << 8) + ((uint32_t)(c ^ (m & 7)) << 4);
        cp16(dst, src + ch);
    }
}

// ---------------------------------------------------------------------------
// tile kernel: symmetric coverage via cyclic offsets, fp16 MMA + fp16 acc.
// ---------------------------------------------------------------------------
__global__ void __launch_bounds__(TPB, 2) tile_kernel() {
    extern __shared__ char smem[];
    uint32_t sb = smem_u32(smem);
    const int tid  = threadIdx.x;
    const int wid  = tid >> 5;
    const int lane = tid & 31;

    const int bi   = blockIdx.x / 3;
    const int grp  = blockIdx.x % 3;
    const int d0   = grp * 16;
    const int ntl  = 16 + ((grp == 2 && bi < 48) ? 1 : 0);
    const int rowbase = bi * 128;

    const int wy  = wid & 1,  wx = wid >> 1;
    const int m0w = wy * 64,  n0w = wx * 32;

    const int bj0 = (bi + d0) % NTILES;
    prefetch_tile(g_h, rowbase, OFF_A, sb, tid);
    prefetch_tile(g_h, bj0 * 128, OFF_B(0), sb, tid);
    if (tid < 32) cp16(sb + OFF_SQJ(0) + tid * 16, g_sq + bj0 * 128 + tid * 4);
    CP_COMMIT();

    unsigned int* colmin = reinterpret_cast<unsigned int*>(smem + OFF_COLMIN);
    if (tid < 128) colmin[tid] = 0x7f800000u;

    float sqi[4][2];
    float rmin[4][2];
    #pragma unroll
    for (int mt = 0; mt < 4; mt++)
        #pragma unroll
        for (int h = 0; h < 2; h++) {
            int r = m0w + mt * 16 + (lane >> 2) + h * 8;
            sqi[mt][h]  = g_sq[rowbase + r];
            rmin[mt][h] = __int_as_float(0x7f800000);
        }

    const int a_rbit = (lane >> 3) & 1;
    const int a_cbit = (lane >> 4) & 1;
    const int b_rbit = (lane >> 4) & 1;
    const int b_cbit = (lane >> 3) & 1;
    const int l7 = lane & 7;

    for (int t = 0; t < ntl; t++) {
        const int b  = t & 1, nb = b ^ 1;
        const int jt = (bi + d0 + t) % NTILES;

        if (t + 1 < ntl) {
            const int jn = (bi + d0 + t + 1) % NTILES;
            prefetch_tile(g_h, jn * 128, OFF_B(nb), sb, tid);
            if (tid < 32)
                cp16(sb + OFF_SQJ(nb) + tid * 16, g_sq + jn * 128 + tid * 4);
            CP_COMMIT();
            CP_WAIT(1);
        } else {
            CP_WAIT(0);
        }
        __syncthreads();

        // ---- MMA: fp16 product, fp16 accumulate, K=128 ----
        uint32_t acc[4][4][2];
        #pragma unroll
        for (int mt = 0; mt < 4; mt++)
            #pragma unroll
            for (int nt = 0; nt < 4; nt++) { acc[mt][nt][0] = 0u; acc[mt][nt][1] = 0u; }

        const uint32_t Ab = sb + OFF_A, Bb = sb + OFF_B(b);

        #pragma unroll
        for (int ks = 0; ks < 8; ks++) {
            const int c0 = ks * 2;
            uint32_t af[4][4], bf[2][4];
            #pragma unroll
            for (int mt = 0; mt < 4; mt++) {
                int row = m0w + mt * 16 + l7 + a_rbit * 8;
                ldsm4(af[mt], Ab + ((uint32_t)row << 8) +
                              ((uint32_t)((c0 + a_cbit) ^ (row & 7)) << 4));
            }
            #pragma unroll
            for (int bt = 0; bt < 2; bt++) {
                int row = n0w + bt * 16 + l7 + b_rbit * 8;
                ldsm4(bf[bt], Bb + ((uint32_t)row << 8) +
                              ((uint32_t)((c0 + b_cbit) ^ (row & 7)) << 4));
            }
            #pragma unroll
            for (int mt = 0; mt < 4; mt++)
                #pragma unroll
                for (int nt = 0; nt < 4; nt++)
                    mma16816h(acc[mt][nt], af[mt],
                              bf[nt >> 1][(nt & 1) * 2],
                              bf[nt >> 1][(nt & 1) * 2 + 1]);
        }

        // ---- epilogue: d^2, mask, row-min regs + col-min ----
        const float* sqj = reinterpret_cast<const float*>(smem + OFF_SQJ(b));
        const bool diag = ((bi & 31) == (jt & 31));
        const float FINF = __int_as_float(0x7f800000);

        float cmin[4][2];
        #pragma unroll
        for (int nt = 0; nt < 4; nt++) { cmin[nt][0] = FINF; cmin[nt][1] = FINF; }

        #pragma unroll
        for (int mt = 0; mt < 4; mt++) {
            const int r0 = m0w + mt * 16 + (lane >> 2);
            const int r1 = r0 + 8;
            #pragma unroll
            for (int nt = 0; nt < 4; nt++) {
                const int c0i = n0w + nt * 8 + (lane & 3) * 2;
                float2 sj = *reinterpret_cast<const float2*>(&sqj[c0i]);
                __half2 h01 = *reinterpret_cast<__half2*>(&acc[mt][nt][0]);
                __half2 h23 = *reinterpret_cast<__half2*>(&acc[mt][nt][1]);
                float2 v01 = __half22float2(h01);
                float2 v23 = __half22float2(h23);
                float d00 = fmaxf(fmaf(v01.x, -2.f, sqi[mt][0] + sj.x), 0.f);
                float d01 = fmaxf(fmaf(v01.y, -2.f, sqi[mt][0] + sj.y), 0.f);
                float d10 = fmaxf(fmaf(v23.x, -2.f, sqi[mt][1] + sj.x), 0.f);
                float d11 = fmaxf(fmaf(v23.y, -2.f, sqi[mt][1] + sj.y), 0.f);
                if (diag) {
                    if (r0 == c0i)     d00 = FINF;
                    if (r0 == c0i + 1) d01 = FINF;
                    if (r1 == c0i)     d10 = FINF;
                    if (r1 == c0i + 1) d11 = FINF;
                }
                rmin[mt][0] = fminf(rmin[mt][0], fminf(d00, d01));
                rmin[mt][1] = fminf(rmin[mt][1], fminf(d10, d11));
                cmin[nt][0] = fminf(cmin[nt][0], fminf(d00, d10));
                cmin[nt][1] = fminf(cmin[nt][1], fminf(d01, d11));
            }
        }

        #pragma unroll
        for (int nt = 0; nt < 4; nt++)
            #pragma unroll
            for (int h = 0; h < 2; h++) {
                float v = cmin[nt][h];
                v = fminf(v, __shfl_xor_sync(0xffffffffu, v, 4));
                v = fminf(v, __shfl_xor_sync(0xffffffffu, v, 8));
                v = fminf(v, __shfl_xor_sync(0xffffffffu, v, 16));
                cmin[nt][h] = v;
            }
        if (lane < 4) {
            #pragma unroll
            for (int nt = 0; nt < 4; nt++) {
                int c = n0w + nt * 8 + lane * 2;
                atomicMin(&colmin[c],     __float_as_uint(cmin[nt][0]));
                atomicMin(&colmin[c + 1], __float_as_uint(cmin[nt][1]));
            }
        }
        __syncthreads();

        if (tid < 128) {
            atomicMin(&g_rowmin[jt * 128 + tid], colmin[tid]);
            colmin[tid] = 0x7f800000u;
        }
    }

    // ---- final row-min: lanes sharing a row, then global atomic ----
    #pragma unroll
    for (int mt = 0; mt < 4; mt++)
        #pragma unroll
        for (int h = 0; h < 2; h++) {
            float v = rmin[mt][h];
            v = fminf(v, __shfl_xor_sync(0xffffffffu, v, 1));
            v = fminf(v, __shfl_xor_sync(0xffffffffu, v, 2));
            if ((lane & 3) == 0) {
                int r = m0w + mt * 16 + (lane >> 2) + h * 8;
                atomicMin(&g_rowmin[rowbase + r], __float_as_uint(v));
            }
        }
}

// ---------------------------------------------------------------------------
// finalize
// ---------------------------------------------------------------------------
__global__ void finalize_kernel(float* __restrict__ out) {
    __shared__ float sl[1024];
    __shared__ float sr[1024];
    int t = threadIdx.x;
    float ls = 0.0f, rs = 0.0f;
    for (int i = t; i < NTOT; i += 1024) {
        float pm = g_posmax[i];
        float nm = __uint_as_float(g_rowmin[i]);
        float pd = (pm > 0.0f) ? sqrtf(pm) : 0.0f;
        float nd = (nm > 0.0f) ? sqrtf(nm) : 0.0f;
        ls += fmaxf(pd - nd + MARGIN, 0.0f);
        rs += g_regpart[i];
    }
    sl[t] = ls; sr[t] = rs;
    __syncthreads();
    #pragma unroll
    for (int s = 512; s; s >>= 1) {
        if (t < s) { sl[t] += sl[t + s]; sr[t] += sr[t + s]; }
        __syncthreads();
    }
    if (t == 0)
        out[0] = sl[0] / (float)NTOT + ALPHA * (sr[0] / (float)(NTOT * DIM));
}

// ---------------------------------------------------------------------------
extern "C" void kernel_launch(void* const* d_in, const int* in_sizes, int n_in,
                              void* d_out, int out_size) {
    const float* a = (const float*)d_in[0];
    const float* p = (const float*)d_in[1];
    const float* n = (const float*)d_in[2];
    float* out = (float*)d_out;

    cudaFuncSetAttribute(tile_kernel,
                         cudaFuncAttributeMaxDynamicSharedMemorySize, SMEM_TOTAL);

    prep_kernel<<<B_SIZE / 8, 256>>>(a, p, n);
    tile_kernel<<<NTILES * 3, TPB, SMEM_TOTAL>>>();
    finalize_kernel<<<1, 1024>>>(out);
}

// round 7
// speedup vs baseline: 7.4861x; 1.0627x over previous
#include <cuda_runtime.h>
#include <cuda_fp16.h>
#include <cstdint>
#include <math.h>

// Inputs: a [4096,128] f32, p [4096,128] f32, n [4096,128] f32. Output: 1 f32.

#define B_SIZE 4096
#define DIM    128
#define NTOT   12288
#define NTILES 96
#define TPB    256
#define MARGIN 0.4f
#define ALPHA  0.01f

// ---- smem layout (bytes) ----
#define OFF_SQJ(b)  ((b) * 512)          // fp32 sqj, per buffer
#define OFF_COLMIN  1024
#define OFF_SQJH(b) (1536 + (b) * 256)   // fp16 sqj, per buffer
#define OFF_A       2048
#define OFF_B(b)    (OFF_A + 32768 + (b) * 32768)
#define SMEM_TOTAL  (OFF_A + 32768 + 2 * 32768)   // 100352

// ---- device scratch ----
__device__ float         g_sq[NTOT];
__device__ __half        g_sqh[NTOT];
__device__ unsigned int  g_rowmin[NTOT];
__device__ float         g_posmax[NTOT];
__device__ float         g_regpart[NTOT];
__device__ __half        g_h[NTOT * DIM];

// ---- helpers ----
__device__ __forceinline__ uint32_t smem_u32(const void* p) {
    uint32_t a;
    asm("{ .reg .u64 t; cvta.to.shared.u64 t, %1; cvt.u32.u64 %0, t; }"
        : "=r"(a) : "l"(p));
    return a;
}
__device__ __forceinline__ void cp16(uint32_t dst, const void* src) {
    asm volatile("cp.async.cg.shared.global [%0], [%1], 16;"
                 :: "r"(dst), "l"(src));
}
#define CP_COMMIT() asm volatile("cp.async.commit_group;" ::: "memory")
#define CP_WAIT(n)  asm volatile("cp.async.wait_group %0;" :: "n"(n) : "memory")

__device__ __forceinline__ void ldsm4(uint32_t* r, uint32_t addr) {
    asm volatile("ldmatrix.sync.aligned.m8n8.x4.shared.b16 {%0,%1,%2,%3}, [%4];"
                 : "=r"(r[0]), "=r"(r[1]), "=r"(r[2]), "=r"(r[3]) : "r"(addr));
}
__device__ __forceinline__ void mma16816h(uint32_t* d, const uint32_t* a,
                                          uint32_t b0, uint32_t b1) {
    asm volatile("mma.sync.aligned.m16n8k16.row.col.f16.f16.f16.f16 "
                 "{%0,%1}, {%2,%3,%4,%5}, {%6,%7}, {%0,%1};"
                 : "+r"(d[0]), "+r"(d[1])
                 : "r"(a[0]), "r"(a[1]), "r"(a[2]), "r"(a[3]),
                   "r"(b0), "r"(b1));
}
__device__ __forceinline__ __half2 shfl_hmin2(__half2 v, int ofs) {
    uint32_t u = __shfl_xor_sync(0xffffffffu,
                                 *reinterpret_cast<uint32_t*>(&v), ofs);
    return __hmin2(v, *reinterpret_cast<__half2*>(&u));
}

// ---------------------------------------------------------------------------
// prep: one warp per column c; loads a_c/p_c/n_c once, emits everything.
// ---------------------------------------------------------------------------
__global__ void __launch_bounds__(256) prep_kernel(const float* __restrict__ a,
                                                   const float* __restrict__ p,
                                                   const float* __restrict__ n) {
    int c    = (blockIdx.x * 256 + threadIdx.x) >> 5;   // 0..4095
    int lane = threadIdx.x & 31;

    float4 xa = reinterpret_cast<const float4*>(a + (size_t)c * DIM)[lane];
    float4 xp = reinterpret_cast<const float4*>(p + (size_t)c * DIM)[lane];
    float4 xn = reinterpret_cast<const float4*>(n + (size_t)c * DIM)[lane];

    float as[4] = {xa.x, xa.y, xa.z, xa.w};
    float ps[4] = {xp.x, xp.y, xp.z, xp.w};
    float ns[4] = {xn.x, xn.y, xn.z, xn.w};

    float sqa = 0.f, sqp = 0.f, sqn = 0.f;
    float ra = 0.f, rp = 0.f, rn = 0.f;
    float eap = 0.f, ean = 0.f, epn = 0.f;
    #pragma unroll
    for (int i = 0; i < 4; i++) {
        sqa += as[i] * as[i];  sqp += ps[i] * ps[i];  sqn += ns[i] * ns[i];
        float ta = fabsf(as[i]) - 1.f; ra += ta * ta;
        float tp = fabsf(ps[i]) - 1.f; rp += tp * tp;
        float tn = fabsf(ns[i]) - 1.f; rn += tn * tn;
        float d1 = as[i] - ps[i]; eap += d1 * d1;
        float d2 = as[i] - ns[i]; ean += d2 * d2;
        float d3 = ps[i] - ns[i]; epn += d3 * d3;
    }
    #pragma unroll
    for (int ofs = 16; ofs; ofs >>= 1) {
        sqa += __shfl_xor_sync(0xffffffffu, sqa, ofs);
        sqp += __shfl_xor_sync(0xffffffffu, sqp, ofs);
        sqn += __shfl_xor_sync(0xffffffffu, sqn, ofs);
        ra  += __shfl_xor_sync(0xffffffffu, ra,  ofs);
        rp  += __shfl_xor_sync(0xffffffffu, rp,  ofs);
        rn  += __shfl_xor_sync(0xffffffffu, rn,  ofs);
        eap += __shfl_xor_sync(0xffffffffu, eap, ofs);
        ean += __shfl_xor_sync(0xffffffffu, ean, ofs);
        epn += __shfl_xor_sync(0xffffffffu, epn, ofs);
    }
    if (lane == 0) {
        g_sq[c]              = sqa;
        g_sq[c + B_SIZE]     = sqp;
        g_sq[c + 2 * B_SIZE] = sqn;
        g_sqh[c]              = __float2half_rn(sqa);
        g_sqh[c + B_SIZE]     = __float2half_rn(sqp);
        g_sqh[c + 2 * B_SIZE] = __float2half_rn(sqn);
        g_regpart[c]              = ra;
        g_regpart[c + B_SIZE]     = rp;
        g_regpart[c + 2 * B_SIZE] = rn;
        g_posmax[c]               = fmaxf(eap, ean);
        g_posmax[c + B_SIZE]      = fmaxf(eap, epn);
        g_posmax[c + 2 * B_SIZE]  = fmaxf(ean, epn);
        g_rowmin[c]               = 0x7f800000u;
        g_rowmin[c + B_SIZE]      = 0x7f800000u;
        g_rowmin[c + 2 * B_SIZE]  = 0x7f800000u;
    }

    #pragma unroll
    for (int seg = 0; seg < 3; seg++) {
        const float* s = (seg == 0) ? as : (seg == 1) ? ps : ns;
        unsigned h0 = 0, h1 = 0;
        #pragma unroll
        for (int i = 0; i < 4; i++) {
            unsigned hb = __half_as_ushort(__float2half_rn(s[i]));
            if (i < 2) h0 |= hb << (16 * i);
            else       h1 |= hb << (16 * (i - 2));
        }
        reinterpret_cast<uint2*>(g_h)[(c + seg * B_SIZE) * 32 + lane] =
            make_uint2(h0, h1);
    }
}

// ---------------------------------------------------------------------------
__device__ __forceinline__ void prefetch_tile(const __half* __restrict__ g,
                                              int rowbase, uint32_t sm_off,
                                              uint32_t sb, int tid) {
    const uint4* src = reinterpret_cast<const uint4*>(g) + (size_t)rowbase * 16;
    #pragma unroll
    for (int i = 0; i < 8; i++) {
        int ch = tid + i * 256;
        int m = ch >> 4, c = ch & 15;
        uint32_t dst = sb + sm_off + ((uint32_t)m << 8) + ((uint32_t)(c ^ (m & 7)) << 4);
        cp16(dst, src + ch);
    }
}
__device__ __forceinline__ void stage_sq(uint32_t sb, int buf, int jt, int tid) {
    if (tid < 32) cp16(sb + OFF_SQJ(buf) + tid * 16, g_sq + jt * 128 + tid * 4);
    else if (tid < 48)
        cp16(sb + OFF_SQJH(buf) + (tid - 32) * 16, g_sqh + jt * 128 + (tid - 32) * 8);
}

// ---------------------------------------------------------------------------
// tile kernel: symmetric cyclic coverage, fp16 MMA/acc, packed fp16 epilogue.
// ---------------------------------------------------------------------------
__global__ void __launch_bounds__(TPB, 2) tile_kernel() {
    extern __shared__ char smem[];
    uint32_t sb = smem_u32(smem);
    const int tid  = threadIdx.x;
    const int wid  = tid >> 5;
    const int lane = tid & 31;

    const int bi   = blockIdx.x / 3;
    const int grp  = blockIdx.x % 3;
    const int d0   = grp * 16;
    const int ntl  = 16 + ((grp == 2 && bi < 48) ? 1 : 0);
    const int rowbase = bi * 128;

    const int wy  = wid & 1,  wx = wid >> 1;
    const int m0w = wy * 64,  n0w = wx * 32;

    const int bj0 = (bi + d0) % NTILES;
    prefetch_tile(g_h, rowbase, OFF_A, sb, tid);
    prefetch_tile(g_h, bj0 * 128, OFF_B(0), sb, tid);
    stage_sq(sb, 0, bj0, tid);
    CP_COMMIT();

    unsigned int* colmin = reinterpret_cast<unsigned int*>(smem + OFF_COLMIN);
    if (tid < 128) colmin[tid] = 0x7f800000u;

    // per-thread row constants: sqi as half2 broadcast (fp32 reloaded at end)
    __half2 sqi2[4][2];
    float   rmin[4][2];
    #pragma unroll
    for (int mt = 0; mt < 4; mt++)
        #pragma unroll
        for (int h = 0; h < 2; h++) {
            int r = m0w + mt * 16 + (lane >> 2) + h * 8;
            sqi2[mt][h] = __float2half2_rn(g_sq[rowbase + r]);
            rmin[mt][h] = __int_as_float(0x7f800000);
        }

    const int a_rbit = (lane >> 3) & 1;
    const int a_cbit = (lane >> 4) & 1;
    const int b_rbit = (lane >> 4) & 1;
    const int b_cbit = (lane >> 3) & 1;
    const int l7 = lane & 7;
    const __half2 NEG2 = __float2half2_rn(-2.0f);
    const __half2 HINF2 = __half2half2(__ushort_as_half(0x7C00));

    for (int t = 0; t < ntl; t++) {
        const int b  = t & 1, nb = b ^ 1;
        const int jt = (bi + d0 + t) % NTILES;

        if (t + 1 < ntl) {
            const int jn = (bi + d0 + t + 1) % NTILES;
            prefetch_tile(g_h, jn * 128, OFF_B(nb), sb, tid);
            stage_sq(sb, nb, jn, tid);
            CP_COMMIT();
            CP_WAIT(1);
        } else {
            CP_WAIT(0);
        }
        __syncthreads();

        // ---- MMA: fp16 product, fp16 accumulate, K=128 ----
        uint32_t acc[4][4][2];
        #pragma unroll
        for (int mt = 0; mt < 4; mt++)
            #pragma unroll
            for (int nt = 0; nt < 4; nt++) { acc[mt][nt][0] = 0u; acc[mt][nt][1] = 0u; }

        const uint32_t Ab = sb + OFF_A, Bb = sb + OFF_B(b);

        #pragma unroll
        for (int ks = 0; ks < 8; ks++) {
            const int c0 = ks * 2;
            uint32_t af[4][4], bf[2][4];
            #pragma unroll
            for (int mt = 0; mt < 4; mt++) {
                int row = m0w + mt * 16 + l7 + a_rbit * 8;
                ldsm4(af[mt], Ab + ((uint32_t)row << 8) +
                              ((uint32_t)((c0 + a_cbit) ^ (row & 7)) << 4));
            }
            #pragma unroll
            for (int bt = 0; bt < 2; bt++) {
                int row = n0w + bt * 16 + l7 + b_rbit * 8;
                ldsm4(bf[bt], Bb + ((uint32_t)row << 8) +
                              ((uint32_t)((c0 + b_cbit) ^ (row & 7)) << 4));
            }
            #pragma unroll
            for (int mt = 0; mt < 4; mt++)
                #pragma unroll
                for (int nt = 0; nt < 4; nt++)
                    mma16816h(acc[mt][nt], af[mt],
                              bf[nt >> 1][(nt & 1) * 2],
                              bf[nt >> 1][(nt & 1) * 2 + 1]);
        }

        // ---- diag masking: splat -inf into dot at same-label positions ----
        if ((bi & 31) == (jt & 31)) {
            #pragma unroll
            for (int mt = 0; mt < 4; mt++) {
                const int r0 = m0w + mt * 16 + (lane >> 2);
                const int r1 = r0 + 8;
                #pragma unroll
                for (int nt = 0; nt < 4; nt++) {
                    const int c0i = n0w + nt * 8 + (lane & 3) * 2;
                    if (r0 == c0i)     acc[mt][nt][0] = (acc[mt][nt][0] & 0xFFFF0000u) | 0x0000FC00u;
                    if (r0 == c0i + 1) acc[mt][nt][0] = (acc[mt][nt][0] & 0x0000FFFFu) | 0xFC000000u;
                    if (r1 == c0i)     acc[mt][nt][1] = (acc[mt][nt][1] & 0xFFFF0000u) | 0x0000FC00u;
                    if (r1 == c0i + 1) acc[mt][nt][1] = (acc[mt][nt][1] & 0x0000FFFFu) | 0xFC000000u;
                }
            }
        }

        // ---- packed epilogue: row partial min_j(sqj-2dot), col min_i(sqi-2dot)
        const __half2* sqjh = reinterpret_cast<const __half2*>(smem + OFF_SQJH(b));
        __half2 rh2[4][2], ch2[4];
        #pragma unroll
        for (int mt = 0; mt < 4; mt++) { rh2[mt][0] = HINF2; rh2[mt][1] = HINF2; }
        #pragma unroll
        for (int nt = 0; nt < 4; nt++) ch2[nt] = HINF2;

        #pragma unroll
        for (int nt = 0; nt < 4; nt++) {
            __half2 sj2 = sqjh[(n0w + nt * 8) / 2 + (lane & 3)];
            #pragma unroll
            for (int mt = 0; mt < 4; mt++) {
                __half2 a0 = *reinterpret_cast<__half2*>(&acc[mt][nt][0]);
                __half2 a1 = *reinterpret_cast<__half2*>(&acc[mt][nt][1]);
                rh2[mt][0] = __hmin2(rh2[mt][0], __hfma2(a0, NEG2, sj2));
                rh2[mt][1] = __hmin2(rh2[mt][1], __hfma2(a1, NEG2, sj2));
                ch2[nt] = __hmin2(ch2[nt], __hfma2(a0, NEG2, sqi2[mt][0]));
                ch2[nt] = __hmin2(ch2[nt], __hfma2(a1, NEG2, sqi2[mt][1]));
            }
        }

        // fold row partials into fp32 running min
        #pragma unroll
        for (int mt = 0; mt < 4; mt++)
            #pragma unroll
            for (int h = 0; h < 2; h++) {
                float2 f = __half22float2(rh2[mt][h]);
                rmin[mt][h] = fminf(rmin[mt][h], fminf(f.x, f.y));
            }

        // col reduce across row-groups (lane>>2) then write smem colmin
        #pragma unroll
        for (int nt = 0; nt < 4; nt++) {
            ch2[nt] = shfl_hmin2(ch2[nt], 4);
            ch2[nt] = shfl_hmin2(ch2[nt], 8);
            ch2[nt] = shfl_hmin2(ch2[nt], 16);
        }
        if (lane < 4) {
            const float* sqjf = reinterpret_cast<const float*>(smem + OFF_SQJ(b));
            #pragma unroll
            for (int nt = 0; nt < 4; nt++) {
                int c = n0w + nt * 8 + lane * 2;
                float2 f = __half22float2(ch2[nt]);
                float v0 = fmaxf(f.x + sqjf[c], 0.f);
                float v1 = fmaxf(f.y + sqjf[c + 1], 0.f);
                atomicMin(&colmin[c],     __float_as_uint(v0));
                atomicMin(&colmin[c + 1], __float_as_uint(v1));
            }
        }
        __syncthreads();

        if (tid < 128) {
            atomicMin(&g_rowmin[jt * 128 + tid], colmin[tid]);
            colmin[tid] = 0x7f800000u;
        }
    }

    // ---- final row-min: add sqi (fp32), reduce column-lanes, atomic ----
    #pragma unroll
    for (int mt = 0; mt < 4; mt++)
        #pragma unroll
        for (int h = 0; h < 2; h++) {
            float v = rmin[mt][h];
            v = fminf(v, __shfl_xor_sync(0xffffffffu, v, 1));
            v = fminf(v, __shfl_xor_sync(0xffffffffu, v, 2));
            if ((lane & 3) == 0) {
                int r = m0w + mt * 16 + (lane >> 2) + h * 8;
                float d2 = fmaxf(v + g_sq[rowbase + r], 0.f);
                atomicMin(&g_rowmin[rowbase + r], __float_as_uint(d2));
            }
        }
}

// ---------------------------------------------------------------------------
__global__ void finalize_kernel(float* __restrict__ out) {
    __shared__ float sl[1024];
    __shared__ float sr[1024];
    int t = threadIdx.x;
    float ls = 0.0f, rs = 0.0f;
    for (int i = t; i < NTOT; i += 1024) {
        float pm = g_posmax[i];
        float nm = __uint_as_float(g_rowmin[i]);
        float pd = (pm > 0.0f) ? sqrtf(pm) : 0.0f;
        float nd = (nm > 0.0f) ? sqrtf(nm) : 0.0f;
        ls += fmaxf(pd - nd + MARGIN, 0.0f);
        rs += g_regpart[i];
    }
    sl[t] = ls; sr[t] = rs;
    __syncthreads();
    #pragma unroll
    for (int s = 512; s; s >>= 1) {
        if (t < s) { sl[t] += sl[t + s]; sr[t] += sr[t + s]; }
        __syncthreads();
    }
    if (t == 0)
        out[0] = sl[0] / (float)NTOT + ALPHA * (sr[0] / (float)(NTOT * DIM));
}

// ---------------------------------------------------------------------------
extern "C" void kernel_launch(void* const* d_in, const int* in_sizes, int n_in,
                              void* d_out, int out_size) {
    const float* a = (const float*)d_in[0];
    const float* p = (const float*)d_in[1];
    const float* n = (const float*)d_in[2];
    float* out = (float*)d_out;

    cudaFuncSetAttribute(tile_kernel,
                         cudaFuncAttributeMaxDynamicSharedMemorySize, SMEM_TOTAL);

    prep_kernel<<<B_SIZE / 8, 256>>>(a, p, n);
    tile_kernel<<<NTILES * 3, TPB, SMEM_TOTAL>>>();
    finalize_kernel<<<1, 1024>>>(out);
}